// round 15
// baseline (speedup 1.0000x reference)
#include <cuda_runtime.h>
#include <cuda_bf16.h>

#define N_GRID 64
#define N1 65
#define W_FEAT 256
#define NCELLS (N_GRID * N_GRID * N_GRID)   // 262144
#define B_MAX 262144

// Scratch (allocation-free rule: __device__ globals).
// g_hist must be zero at first use: static zero-init gives that, and
// scan_block_kernel resets it each pass so graph replays stay correct.
__device__ int    g_hist[NCELLS];      // zero-initialized
__device__ int    g_offsets[NCELLS];   // exclusive prefix within 1024-chunk
__device__ int    g_blocksums[256];    // RAW chunk totals (scanned inline in scatter)
__device__ int    g_cell[B_MAX];
__device__ float4 g_pts[B_MAX];        // sorted payload: (x, y, z, bitcast(point id))

__global__ void hist_kernel(const float* __restrict__ x, int B) {
    int p = blockIdx.x * blockDim.x + threadIdx.x;
    if (p >= B) return;
    const float scale = (float)N_GRID / 2.0f;
    float rx = (x[p * 3 + 0] + 1.0f) * scale;
    float ry = (x[p * 3 + 1] + 1.0f) * scale;
    float rz = (x[p * 3 + 2] + 1.0f) * scale;
    int ix = min(max((int)floorf(rx), 0), N_GRID - 1);
    int iy = min(max((int)floorf(ry), 0), N_GRID - 1);
    int iz = min(max((int)floorf(rz), 0), N_GRID - 1);
    int cell = (ix * N_GRID + iy) * N_GRID + iz;   // lexicographic = memory order
    g_cell[p] = cell;
    atomicAdd(&g_hist[cell], 1);
}

// 256 blocks x 1024 threads: shuffle-based exclusive scan of each 1024-chunk
// into g_offsets, reset g_hist, emit RAW chunk total.
__global__ void __launch_bounds__(1024) scan_block_kernel() {
    __shared__ int wsum[32];
    int tid = threadIdx.x;
    int lane = tid & 31;
    int wid = tid >> 5;
    int i = blockIdx.x * 1024 + tid;

    int v = g_hist[i];
    int inc = v;
    #pragma unroll
    for (int off = 1; off < 32; off <<= 1) {
        int t = __shfl_up_sync(0xFFFFFFFF, inc, off);
        if (lane >= off) inc += t;
    }
    if (lane == 31) wsum[wid] = inc;
    __syncthreads();
    if (wid == 0) {
        int ws = wsum[lane];
        int winc = ws;
        #pragma unroll
        for (int off = 1; off < 32; off <<= 1) {
            int t = __shfl_up_sync(0xFFFFFFFF, winc, off);
            if (lane >= off) winc += t;
        }
        wsum[lane] = winc - ws;      // exclusive warp prefix
    }
    __syncthreads();
    int excl = inc - v + wsum[wid];
    g_offsets[i] = excl;
    g_hist[i] = 0;                   // ready for next replay
    if (tid == 1023) g_blocksums[blockIdx.x] = excl + v;  // raw chunk total
}

// 1024 blocks x 256 threads. Each block first scans the 256 raw chunk totals
// in smem, then scatters 256 points as float4 payloads into sorted order.
__global__ void __launch_bounds__(256) scatter_kernel(const float* __restrict__ x, int B) {
    __shared__ int bs[256];
    __shared__ int wsum[8];
    int tid = threadIdx.x;
    int lane = tid & 31;
    int wid = tid >> 5;

    int raw = g_blocksums[tid];
    int inc = raw;
    #pragma unroll
    for (int off = 1; off < 32; off <<= 1) {
        int t = __shfl_up_sync(0xFFFFFFFF, inc, off);
        if (lane >= off) inc += t;
    }
    if (lane == 31) wsum[wid] = inc;
    __syncthreads();
    if (wid == 0 && lane < 8) {
        int ws = wsum[lane];
        int winc = ws;
        #pragma unroll
        for (int off = 1; off < 8; off <<= 1) {
            int t = __shfl_up_sync(0x000000FF, winc, off);
            if (lane >= off) winc += t;
        }
        wsum[lane] = winc - ws;      // exclusive warp prefix
    }
    __syncthreads();
    bs[tid] = inc - raw + wsum[wid]; // exclusive prefix of chunk totals
    __syncthreads();

    int p = blockIdx.x * 256 + tid;
    if (p >= B) return;
    int c = g_cell[p];
    int pos = atomicAdd(&g_offsets[c], 1) + bs[c >> 10];
    g_pts[pos] = make_float4(x[p * 3 + 0], x[p * 3 + 1], x[p * 3 + 2],
                             __int_as_float(p));
}

// Thread-per-point scalar grid_value interpolation, in sorted order.
__global__ void __launch_bounds__(256) gridval_kernel(
    const float* __restrict__ grid_value,
    float* __restrict__ out_val,
    int B)
{
    int i = blockIdx.x * blockDim.x + threadIdx.x;
    if (i >= B) return;

    float4 pt = __ldg(&g_pts[i]);
    int p = __float_as_int(pt.w);

    const float scale = (float)N_GRID / 2.0f;
    float rx = (pt.x + 1.0f) * scale;
    float ry = (pt.y + 1.0f) * scale;
    float rz = (pt.z + 1.0f) * scale;

    bool valid = (rx >= 0.0f) && (rx <= (float)N_GRID) &&
                 (ry >= 0.0f) && (ry <= (float)N_GRID) &&
                 (rz >= 0.0f) && (rz <= (float)N_GRID);

    int ix = min(max((int)floorf(rx), 0), N_GRID - 1);
    int iy = min(max((int)floorf(ry), 0), N_GRID - 1);
    int iz = min(max((int)floorf(rz), 0), N_GRID - 1);

    float tx = rx - (float)ix;
    float ty = ry - (float)iy;
    float tz = rz - (float)iz;

    int base = (ix * N1 + iy) * N1 + iz;

    float wx0 = 1.0f - tx, wx1 = tx;
    float wy0 = 1.0f - ty, wy1 = ty;
    float wz0 = 1.0f - tz, wz1 = tz;

    float v000 = __ldg(&grid_value[base]);
    float v001 = __ldg(&grid_value[base + 1]);
    float v010 = __ldg(&grid_value[base + N1]);
    float v011 = __ldg(&grid_value[base + N1 + 1]);
    float v100 = __ldg(&grid_value[base + N1 * N1]);
    float v101 = __ldg(&grid_value[base + N1 * N1 + 1]);
    float v110 = __ldg(&grid_value[base + N1 * N1 + N1]);
    float v111 = __ldg(&grid_value[base + N1 * N1 + N1 + 1]);

    float s = wx0 * wy0 * wz0 * v000 + wx0 * wy0 * wz1 * v001
            + wx0 * wy1 * wz0 * v010 + wx0 * wy1 * wz1 * v011
            + wx1 * wy0 * wz0 * v100 + wx1 * wy0 * wz1 * v101
            + wx1 * wy1 * wz0 * v110 + wx1 * wy1 * wz1 * v111;

    out_val[p] = valid ? s : 0.0f;
}

// Per-point setup: weights, base cell, validity, output id.
struct PointW {
    int   base;
    int   p;
    bool  valid;
    float w[8];
};

__device__ __forceinline__ PointW make_pointw(float4 pt) {
    PointW r;
    r.p = __float_as_int(pt.w);
    const float scale = (float)N_GRID / 2.0f;
    float rx = (pt.x + 1.0f) * scale;
    float ry = (pt.y + 1.0f) * scale;
    float rz = (pt.z + 1.0f) * scale;
    r.valid = (rx >= 0.0f) && (rx <= (float)N_GRID) &&
              (ry >= 0.0f) && (ry <= (float)N_GRID) &&
              (rz >= 0.0f) && (rz <= (float)N_GRID);
    int ix = min(max((int)floorf(rx), 0), N_GRID - 1);
    int iy = min(max((int)floorf(ry), 0), N_GRID - 1);
    int iz = min(max((int)floorf(rz), 0), N_GRID - 1);
    float tx = rx - (float)ix, ty = ry - (float)iy, tz = rz - (float)iz;
    r.base = (ix * N1 + iy) * N1 + iz;
    float wx0 = 1.0f - tx, wx1 = tx;
    float wy0 = 1.0f - ty, wy1 = ty;
    float wz0 = 1.0f - tz, wz1 = tz;
    r.w[0] = wx0 * wy0 * wz0;
    r.w[1] = wx0 * wy0 * wz1;
    r.w[2] = wx0 * wy1 * wz0;
    r.w[3] = wx0 * wy1 * wz1;
    r.w[4] = wx1 * wy0 * wz0;
    r.w[5] = wx1 * wy0 * wz1;
    r.w[6] = wx1 * wy1 * wz0;
    r.w[7] = wx1 * wy1 * wz1;
    return r;
}

__device__ __forceinline__ void store_feat(float* __restrict__ out_feat,
                                           int p, int lane,
                                           float4 v0, float4 v1) {
    // streaming stores: out_feat is write-once, keep it out of L2's way
    float4* fo = (float4*)(out_feat + (size_t)p * W_FEAT);
    __stcs(&fo[lane], v0);
    __stcs(&fo[lane + 32], v1);
}

// Warp per PAIR of consecutive sorted points.
// Same cell  -> one load pass feeds both accumulator sets.
// Diff cells -> A and B corner loads interleaved (2x in-flight loads).
// Branch is warp-uniform (cell ids identical across lanes).
__global__ void __launch_bounds__(128) trilerp_kernel(
    const float* __restrict__ grid_feature,
    float* __restrict__ out_feat,
    int B)
{
    int pw = (blockIdx.x * blockDim.x + threadIdx.x) >> 5;  // pair index
    int lane = threadIdx.x & 31;
    int i0 = pw * 2;
    if (i0 >= B) return;
    bool haveB = (i0 + 1 < B);

    float4 ptA = __ldg(&g_pts[i0]);
    float4 ptB = haveB ? __ldg(&g_pts[i0 + 1]) : ptA;

    PointW A = make_pointw(ptA);
    PointW Bq = make_pointw(ptB);

    float4 a0 = make_float4(0.f, 0.f, 0.f, 0.f);
    float4 a1 = make_float4(0.f, 0.f, 0.f, 0.f);
    float4 b0 = make_float4(0.f, 0.f, 0.f, 0.f);
    float4 b1 = make_float4(0.f, 0.f, 0.f, 0.f);

    if (haveB && Bq.base == A.base) {
        // shared loads, dual accumulation (per-point FMA order preserved)
        #pragma unroll
        for (int c = 0; c < 8; c++) {
            int off = (((c >> 2) & 1) * (N1 * N1) + ((c >> 1) & 1) * N1 + (c & 1));
            const float4* row = (const float4*)(grid_feature + (size_t)(A.base + off) * W_FEAT);
            float4 f0 = __ldg(&row[lane]);
            float4 f1 = __ldg(&row[lane + 32]);
            float wa = A.w[c], wb = Bq.w[c];
            a0.x += wa * f0.x; a0.y += wa * f0.y; a0.z += wa * f0.z; a0.w += wa * f0.w;
            a1.x += wa * f1.x; a1.y += wa * f1.y; a1.z += wa * f1.z; a1.w += wa * f1.w;
            b0.x += wb * f0.x; b0.y += wb * f0.y; b0.z += wb * f0.z; b0.w += wb * f0.w;
            b1.x += wb * f1.x; b1.y += wb * f1.y; b1.z += wb * f1.z; b1.w += wb * f1.w;
        }
    } else {
        // distinct cells: interleave A and B loads -> 2x loads in flight
        #pragma unroll
        for (int c = 0; c < 8; c++) {
            int off = (((c >> 2) & 1) * (N1 * N1) + ((c >> 1) & 1) * N1 + (c & 1));
            const float4* rowA = (const float4*)(grid_feature + (size_t)(A.base + off) * W_FEAT);
            const float4* rowB = (const float4*)(grid_feature + (size_t)(Bq.base + off) * W_FEAT);
            float4 fA0 = __ldg(&rowA[lane]);
            float4 fA1 = __ldg(&rowA[lane + 32]);
            float4 fB0 = __ldg(&rowB[lane]);
            float4 fB1 = __ldg(&rowB[lane + 32]);
            float wa = A.w[c], wb = Bq.w[c];
            a0.x += wa * fA0.x; a0.y += wa * fA0.y; a0.z += wa * fA0.z; a0.w += wa * fA0.w;
            a1.x += wa * fA1.x; a1.y += wa * fA1.y; a1.z += wa * fA1.z; a1.w += wa * fA1.w;
            b0.x += wb * fB0.x; b0.y += wb * fB0.y; b0.z += wb * fB0.z; b0.w += wb * fB0.w;
            b1.x += wb * fB1.x; b1.y += wb * fB1.y; b1.z += wb * fB1.z; b1.w += wb * fB1.w;
        }
    }

    if (!A.valid)  { a0 = make_float4(0,0,0,0); a1 = make_float4(0,0,0,0); }
    store_feat(out_feat, A.p, lane, a0, a1);
    if (haveB) {
        if (!Bq.valid) { b0 = make_float4(0,0,0,0); b1 = make_float4(0,0,0,0); }
        store_feat(out_feat, Bq.p, lane, b0, b1);
    }
}

extern "C" void kernel_launch(void* const* d_in, const int* in_sizes, int n_in,
                              void* d_out, int out_size) {
    const float* x            = (const float*)d_in[0];
    const float* grid_value   = (const float*)d_in[1];
    const float* grid_feature = (const float*)d_in[2];

    int B = in_sizes[0] / 3;

    float* out_val  = (float*)d_out;        // (B, 1)
    float* out_feat = out_val + B;          // (B, 256)

    // --- counting sort by full cell id ---
    hist_kernel<<<(B + 255) / 256, 256>>>(x, B);
    scan_block_kernel<<<NCELLS / 1024, 1024>>>();
    scatter_kernel<<<(B + 255) / 256, 256>>>(x, B);

    // --- scalar grid_value path: thread per point, sorted (coalesced) ---
    gridval_kernel<<<(B + 255) / 256, 256>>>(grid_value, out_val, B);

    // --- feature gather: warp per sorted PAIR, interleaved loads ---
    int pairs = (B + 1) / 2;
    int warps_per_block = 4;                 // 128 threads
    int blocks = (pairs + warps_per_block - 1) / warps_per_block;
    trilerp_kernel<<<blocks, 128>>>(grid_feature, out_feat, B);
}